// round 1
// baseline (speedup 1.0000x reference)
#include <cuda_runtime.h>
#include <math.h>

#define NROWS 131072   // B*T*NN = 128*128*8
// B=128, T=128, NN=8, C=64, F_IN=32

__device__ float g_dinv[NROWS];
__device__ float g_bufA[NROWS * 64];
__device__ float g_bufB[NROWS * 64];
__device__ float g_bufC[NROWS * 64];
__device__ float g_stats[128];   // [0:64) sum, [64:128) sumsq
__device__ float g_scale[64];
__device__ float g_shift[64];
__device__ float g_wsum[72];     // [0:64) row-sums of reg_w, [64] = sum(reg_b)

// ---------------------------------------------------------------- degree
__global__ void k_deg_init() {
    int i = blockIdx.x * 256 + threadIdx.x;
    if (i < NROWS) g_dinv[i] = 1.0f;   // self loop
}
__global__ void k_deg_acc(const int* __restrict__ dst, int E) {
    int e = blockIdx.x * 256 + threadIdx.x;
    if (e < E) atomicAdd(&g_dinv[dst[e]], 1.0f);
}
__global__ void k_dinv_fin() {
    int i = blockIdx.x * 256 + threadIdx.x;
    if (i < NROWS) g_dinv[i] = rsqrtf(g_dinv[i]);
}

// ---------------------------------------------------- self-loop init (+ stat zero)
template<int F>
__global__ void k_selfloop(const float* __restrict__ X, float* __restrict__ Y) {
    int idx = blockIdx.x * 256 + threadIdx.x;
    if (idx < 128) g_stats[idx] = 0.0f;
    const int CH = F / 4;
    if (idx >= NROWS * CH) return;
    int row = idx / CH;
    float dv = g_dinv[row];
    float c = dv * dv;
    float4 v = reinterpret_cast<const float4*>(X)[idx];
    v.x *= c; v.y *= c; v.z *= c; v.w *= c;
    reinterpret_cast<float4*>(Y)[idx] = v;
}

// ---------------------------------------------------------------- edge scatter
template<int F>
__global__ void k_scatter(const float* __restrict__ X, float* __restrict__ Y,
                          const int* __restrict__ src, const int* __restrict__ dst, int E) {
    const int CH = F / 4;
    unsigned idx = blockIdx.x * 256u + threadIdx.x;
    if (idx >= (unsigned)E * CH) return;
    int e = idx / CH;
    int c = idx - e * CH;
    int s = src[e], d = dst[e];
    float coef = g_dinv[s] * g_dinv[d];
    float4 v = reinterpret_cast<const float4*>(X)[(size_t)s * CH + c];
    float* yp = Y + (size_t)d * F + c * 4;
    atomicAdd(yp + 0, v.x * coef);
    atomicAdd(yp + 1, v.y * coef);
    atomicAdd(yp + 2, v.z * coef);
    atomicAdd(yp + 3, v.w * coef);
}

// ---------------------------------------------------------------- unified GEMM
// C[N,64] = A_tile @ W + bias, 128-row tiles, 256 threads, 8x4 per thread.
// TAPS: 1 = plain, 3 = temporal conv (row shift +/-8 with t-boundary masking)
// AMODE: 0 = plain A load, 1 = BN+ReLU transform on A load (uses g_scale/g_shift)
// WLAYOUT: 0 = W[k][c] contiguous, 1 = W[c][k] (1x1 conv), 2 = W[c][k][3] tap (temporal)
// EMODE: 0 = plain store, 1 = plain store + BN-stat accumulation,
//        2 = tanh + scrambled (B,C,NN,T)-layout store (reproduces ref's .view bug)
template<int K, int TAPS, int AMODE, int WLAYOUT, int EMODE>
__global__ void __launch_bounds__(256)
k_gemm(const float* __restrict__ A, const float* __restrict__ W,
       const float* __restrict__ bias, float* __restrict__ out) {
    __shared__ float  Asm[128 * K];
    __shared__ float4 Wsm[K * 16];
    const int tid = threadIdx.x;
    const int cg = tid & 15, rg = tid >> 4;
    const int c0 = cg * 4, r0 = rg * 8;
    const int row0 = blockIdx.x << 7;

    float4 acc[8];
    {
        float4 bb = reinterpret_cast<const float4*>(bias)[cg];
        #pragma unroll
        for (int i = 0; i < 8; i++) acc[i] = bb;
    }

    for (int tap = 0; tap < TAPS; ++tap) {
        __syncthreads();
        const int CH = K / 4;
        #pragma unroll
        for (int idx = tid; idx < 128 * CH; idx += 256) {
            int rr = idx / CH;
            int kc = idx - rr * CH;
            float4 v;
            if (TAPS == 3) {
                int grow = row0 + rr;
                int dlt = tap - 1;
                int ts = ((grow >> 3) & 127) + dlt;
                if ((unsigned)ts < 128u)
                    v = reinterpret_cast<const float4*>(A + (size_t)(grow + dlt * 8) * K)[kc];
                else
                    v = make_float4(0.f, 0.f, 0.f, 0.f);
            } else {
                v = reinterpret_cast<const float4*>(A)[(size_t)(row0 + rr) * CH + kc];
            }
            if (AMODE == 1) {
                int k4 = kc * 4;
                v.x = fmaxf(0.f, fmaf(v.x, g_scale[k4 + 0], g_shift[k4 + 0]));
                v.y = fmaxf(0.f, fmaf(v.y, g_scale[k4 + 1], g_shift[k4 + 1]));
                v.z = fmaxf(0.f, fmaf(v.z, g_scale[k4 + 2], g_shift[k4 + 2]));
                v.w = fmaxf(0.f, fmaf(v.w, g_scale[k4 + 3], g_shift[k4 + 3]));
            }
            reinterpret_cast<float4*>(Asm)[idx] = v;
        }
        #pragma unroll
        for (int idx = tid; idx < K * 16; idx += 256) {
            int k = idx >> 4, cc = (idx & 15) * 4;
            float4 w;
            if (WLAYOUT == 0) {
                w = reinterpret_cast<const float4*>(W)[idx];
            } else if (WLAYOUT == 1) {
                w.x = W[(cc + 0) * 64 + k]; w.y = W[(cc + 1) * 64 + k];
                w.z = W[(cc + 2) * 64 + k]; w.w = W[(cc + 3) * 64 + k];
            } else {
                w.x = W[(cc + 0) * 192 + k * 3 + tap]; w.y = W[(cc + 1) * 192 + k * 3 + tap];
                w.z = W[(cc + 2) * 192 + k * 3 + tap]; w.w = W[(cc + 3) * 192 + k * 3 + tap];
            }
            Wsm[idx] = w;
        }
        __syncthreads();
        #pragma unroll 4
        for (int k = 0; k < K; k++) {
            float4 w = Wsm[(k << 4) + cg];
            #pragma unroll
            for (int i = 0; i < 8; i++) {
                float a = Asm[(r0 + i) * K + k];
                acc[i].x = fmaf(a, w.x, acc[i].x);
                acc[i].y = fmaf(a, w.y, acc[i].y);
                acc[i].z = fmaf(a, w.z, acc[i].z);
                acc[i].w = fmaf(a, w.w, acc[i].w);
            }
        }
    }

    if (EMODE == 0 || EMODE == 1) {
        #pragma unroll
        for (int i = 0; i < 8; i++)
            *reinterpret_cast<float4*>(out + (size_t)(row0 + r0 + i) * 64 + c0) = acc[i];
    }
    if (EMODE == 1) {
        float* red = Asm;            // reuse A tile smem for the channel reduction
        __syncthreads();
        if (tid < 128) red[tid] = 0.f;
        __syncthreads();
        const float* accf = reinterpret_cast<const float*>(acc);
        #pragma unroll
        for (int j = 0; j < 4; j++) {
            float s = 0.f, s2 = 0.f;
            #pragma unroll
            for (int i = 0; i < 8; i++) { float v = accf[i * 4 + j]; s += v; s2 += v * v; }
            atomicAdd(&red[c0 + j], s);
            atomicAdd(&red[64 + c0 + j], s2);
        }
        __syncthreads();
        if (tid < 128) atomicAdd(&g_stats[tid], red[tid]);
    }
    if (EMODE == 2) {
        #pragma unroll
        for (int i = 0; i < 8; i++) {
            int grow = row0 + r0 + i;
            int b = grow >> 10, t = (grow >> 3) & 127, nn = grow & 7;
            size_t base = ((((size_t)b * 64 + c0) * 8 + nn) << 7) + t;
            out[base       ] = tanhf(acc[i].x);
            out[base + 1024] = tanhf(acc[i].y);   // co+1 -> +NN*T
            out[base + 2048] = tanhf(acc[i].z);
            out[base + 3072] = tanhf(acc[i].w);
        }
    }
}

// ---------------------------------------------------------------- BN finalize
__global__ void k_bn_fin(const float* __restrict__ g, const float* __restrict__ b) {
    int c = threadIdx.x;
    if (c >= 64) return;
    const float inv = 1.0f / (float)NROWS;
    float mean = g_stats[c] * inv;
    float var  = g_stats[64 + c] * inv - mean * mean;
    float sc = rsqrtf(var + 1e-5f) * g[c];
    g_scale[c] = sc;
    g_shift[c] = b[c] - mean * sc;
}

// ------------------------------------------------- regression prep + final reduce
__global__ void k_prep_reg(const float* __restrict__ rw, const float* __restrict__ rb,
                           float* __restrict__ out) {
    int t = blockIdx.x * 256 + threadIdx.x;
    if (t < 1024) out[t] = 0.0f;
    if (t < 64) {
        float s = 0.f;
        #pragma unroll
        for (int k = 0; k < 8; k++) s += rw[t * 8 + k];
        g_wsum[t] = s;
    }
    if (t == 0) {
        float s = 0.f;
        #pragma unroll
        for (int k = 0; k < 8; k++) s += rb[k];
        g_wsum[64] = s;
    }
}

__global__ void k_reg(const float* __restrict__ X, float* __restrict__ out) {
    int r = blockIdx.x * 256 + threadIdx.x;
    if (r >= NROWS) return;
    const float4* xp = reinterpret_cast<const float4*>(X + (size_t)r * 64);
    float s = 0.f;
    #pragma unroll
    for (int q = 0; q < 16; q++) {
        float4 v = xp[q];
        s += v.x * g_wsum[q * 4 + 0] + v.y * g_wsum[q * 4 + 1]
           + v.z * g_wsum[q * 4 + 2] + v.w * g_wsum[q * 4 + 3];
    }
    float val = (s + g_wsum[64]) * (1.0f / 1024.0f);
    atomicAdd(&out[((r >> 10) << 3) + (r & 7)], val);
}

// ---------------------------------------------------------------- launch
extern "C" void kernel_launch(void* const* d_in, const int* in_sizes, int n_in,
                              void* d_out, int out_size) {
    const float* x      = (const float*)d_in[0];
    const int*   ei     = (const int*)  d_in[1];
    const float* gcn1_w = (const float*)d_in[2];
    const float* gcn1_b = (const float*)d_in[3];
    const float* t1_w   = (const float*)d_in[4];
    const float* t1_b   = (const float*)d_in[5];
    const float* bn1_g  = (const float*)d_in[6];
    const float* bn1_b  = (const float*)d_in[7];
    const float* o1_w   = (const float*)d_in[8];
    const float* o1_b   = (const float*)d_in[9];
    const float* gcn2_w = (const float*)d_in[10];
    const float* gcn2_b = (const float*)d_in[11];
    const float* t2_w   = (const float*)d_in[12];
    const float* t2_b   = (const float*)d_in[13];
    const float* bn2_g  = (const float*)d_in[14];
    const float* bn2_b  = (const float*)d_in[15];
    const float* o2_w   = (const float*)d_in[16];
    const float* o2_b   = (const float*)d_in[17];
    const float* reg_w  = (const float*)d_in[18];
    const float* reg_b  = (const float*)d_in[19];
    float* out = (float*)d_out;

    int E = in_sizes[1] / 2;
    const int* src = ei;
    const int* dst = ei + E;

    float *bufA, *bufB, *bufC;
    cudaGetSymbolAddress((void**)&bufA, g_bufA);
    cudaGetSymbolAddress((void**)&bufB, g_bufB);
    cudaGetSymbolAddress((void**)&bufC, g_bufC);

    // degree + dinv (recomputed each call; cheap, deterministic)
    k_deg_init<<<NROWS / 256, 256>>>();
    k_deg_acc<<<(E + 255) / 256, 256>>>(dst, E);
    k_dinv_fin<<<NROWS / 256, 256>>>();

    // ---- layer 1: GCN aggregates in 32-d input space (A(XW) = (AX)W)
    k_selfloop<32><<<(NROWS * 8 + 255) / 256, 256>>>(x, bufA);           // also zeroes stats
    k_scatter<32><<<((unsigned)E * 8 + 255) / 256, 256>>>(x, bufA, src, dst, E);
    k_gemm<32, 1, 0, 0, 0><<<1024, 256>>>(bufA, gcn1_w, gcn1_b, bufB);   // H1
    k_gemm<64, 3, 0, 2, 1><<<1024, 256>>>(bufB, t1_w, t1_b, bufC);       // tconv1 + stats
    k_bn_fin<<<1, 64>>>(bn1_g, bn1_b);
    k_gemm<64, 1, 1, 1, 2><<<1024, 256>>>(bufC, o1_w, o1_b, bufA);       // bn+relu+1x1+tanh -> scrambled x2

    // ---- layer 2
    k_selfloop<64><<<(NROWS * 16 + 255) / 256, 256>>>(bufA, bufB);       // also zeroes stats
    k_scatter<64><<<((unsigned)E * 16 + 255) / 256, 256>>>(bufA, bufB, src, dst, E);
    k_gemm<64, 1, 0, 0, 0><<<1024, 256>>>(bufB, gcn2_w, gcn2_b, bufC);   // H2
    k_gemm<64, 3, 0, 2, 1><<<1024, 256>>>(bufC, t2_w, t2_b, bufB);       // tconv2 + stats
    k_bn_fin<<<1, 64>>>(bn2_g, bn2_b);
    k_gemm<64, 1, 1, 1, 2><<<1024, 256>>>(bufB, o2_w, o2_b, bufC);       // -> scrambled x3

    // ---- regression + mean over (T, 8)
    k_prep_reg<<<4, 256>>>(reg_w, reg_b, out);
    k_reg<<<NROWS / 256, 256>>>(bufC, out);
}